// round 1
// baseline (speedup 1.0000x reference)
#include <cuda_runtime.h>
#include <math.h>

// Problem constants
#define DIMC   2048
#define CTXD   4096
#define NH     16
#define HD     128
#define LQ     8192
#define SK     512

// Scratch (static device globals — allowed; no runtime allocation)
__device__ float g_qbuf[(long long)LQ * DIMC];          // 67 MB
__device__ float g_kbuf[(long long)SK * DIMC];          // 4 MB
__device__ float g_vbuf[(long long)SK * DIMC];          // 4 MB
__device__ float g_attn[(long long)LQ * DIMC];          // 67 MB
__device__ float g_scores[(long long)NH * LQ * SK];     // 268 MB

// ---------------------------------------------------------------------------
// Tiled SGEMM: C = alpha * A @ B(^T) + bias
//   A: [M,K] row-major (lda), B: NN -> [K,N] (ldb) / NT -> [N,K] (ldb)
//   Batched over blockIdx.z via element strides (used for per-head slices).
//   Requires: M%128==0, N%128==0, K%16==0 (true for all calls here).
// ---------------------------------------------------------------------------
template <bool TB>
__global__ __launch_bounds__(256)
void gemm_tiled(const float* __restrict__ A, const float* __restrict__ B,
                const float* __restrict__ bias, float* __restrict__ C,
                int M, int N, int K, int lda, int ldb, int ldc, float alpha,
                long long aBatch, long long bBatch, long long cBatch)
{
    constexpr int BM = 128, BN = 128, BK = 16;
    __shared__ float As[BK][BM];
    __shared__ float Bs[BK][BN];

    A += (long long)blockIdx.z * aBatch;
    B += (long long)blockIdx.z * bBatch;
    C += (long long)blockIdx.z * cBatch;

    const int bm  = blockIdx.y * BM;
    const int bn  = blockIdx.x * BN;
    const int tid = threadIdx.x;

    // A / NT-B loader: 128 rows x 16 cols as float4, 2 rows per thread
    const int arow = tid >> 2;            // 0..63
    const int acol = (tid & 3) * 4;       // 0,4,8,12
    // NN-B loader: 16 rows x 128 cols as float4, 2 rows per thread
    const int brow = tid >> 5;            // 0..7
    const int bcol = (tid & 31) * 4;

    const int ty = tid >> 4;              // 0..15 (row group)
    const int tx = tid & 15;              // 0..15 (col group)

    float acc[8][8] = {};

    for (int k0 = 0; k0 < K; k0 += BK) {
        // --- load A tile (transpose into As[k][m]) ---
        #pragma unroll
        for (int i = 0; i < 2; i++) {
            int r = arow + i * 64;
            float4 v = *(const float4*)&A[(long long)(bm + r) * lda + k0 + acol];
            As[acol + 0][r] = v.x; As[acol + 1][r] = v.y;
            As[acol + 2][r] = v.z; As[acol + 3][r] = v.w;
        }
        // --- load B tile into Bs[k][n] ---
        if (TB) {
            #pragma unroll
            for (int i = 0; i < 2; i++) {
                int r = arow + i * 64;     // n index
                float4 v = *(const float4*)&B[(long long)(bn + r) * ldb + k0 + acol];
                Bs[acol + 0][r] = v.x; Bs[acol + 1][r] = v.y;
                Bs[acol + 2][r] = v.z; Bs[acol + 3][r] = v.w;
            }
        } else {
            #pragma unroll
            for (int i = 0; i < 2; i++) {
                int r = brow + i * 8;      // k index
                float4 v = *(const float4*)&B[(long long)(k0 + r) * ldb + bn + bcol];
                *(float4*)&Bs[r][bcol] = v;
            }
        }
        __syncthreads();

        #pragma unroll
        for (int kk = 0; kk < BK; kk++) {
            float a[8], b[8];
            *(float4*)&a[0] = *(const float4*)&As[kk][ty * 8];
            *(float4*)&a[4] = *(const float4*)&As[kk][ty * 8 + 4];
            *(float4*)&b[0] = *(const float4*)&Bs[kk][tx * 8];
            *(float4*)&b[4] = *(const float4*)&Bs[kk][tx * 8 + 4];
            #pragma unroll
            for (int i = 0; i < 8; i++)
                #pragma unroll
                for (int j = 0; j < 8; j++)
                    acc[i][j] += a[i] * b[j];
        }
        __syncthreads();
    }

    // --- epilogue: alpha scale + optional bias, vectorized stores ---
    #pragma unroll
    for (int i = 0; i < 8; i++) {
        const long long row = bm + ty * 8 + i;
        #pragma unroll
        for (int j = 0; j < 8; j += 4) {
            const int col = bn + tx * 8 + j;
            float4 v;
            v.x = acc[i][j + 0] * alpha;
            v.y = acc[i][j + 1] * alpha;
            v.z = acc[i][j + 2] * alpha;
            v.w = acc[i][j + 3] * alpha;
            if (bias) {
                v.x += bias[col + 0]; v.y += bias[col + 1];
                v.z += bias[col + 2]; v.w += bias[col + 3];
            }
            *(float4*)&C[row * ldc + col] = v;
        }
    }
}

// ---------------------------------------------------------------------------
// Reductions
// ---------------------------------------------------------------------------
__device__ __forceinline__ float warp_sum(float v) {
    #pragma unroll
    for (int o = 16; o > 0; o >>= 1) v += __shfl_xor_sync(0xffffffffu, v, o);
    return v;
}
__device__ __forceinline__ float warp_max(float v) {
    #pragma unroll
    for (int o = 16; o > 0; o >>= 1) v = fmaxf(v, __shfl_xor_sync(0xffffffffu, v, o));
    return v;
}

// In-place RMSNorm over rows of 2048, with learned weight g. 256 threads/row.
__global__ __launch_bounds__(256)
void rmsnorm_kernel(float* __restrict__ buf, const float* __restrict__ g)
{
    float* p = buf + (long long)blockIdx.x * DIMC;
    const int t = threadIdx.x;
    float v[8];
    float ss = 0.f;
    #pragma unroll
    for (int i = 0; i < 8; i++) { v[i] = p[t + i * 256]; ss += v[i] * v[i]; }
    ss = warp_sum(ss);
    __shared__ float sh[8];
    if ((t & 31) == 0) sh[t >> 5] = ss;
    __syncthreads();
    float tot = 0.f;
    #pragma unroll
    for (int i = 0; i < 8; i++) tot += sh[i];
    const float inv = rsqrtf(tot * (1.0f / DIMC) + 1e-6f);
    #pragma unroll
    for (int i = 0; i < 8; i++) p[t + i * 256] = v[i] * inv * g[t + i * 256];
}

// Softmax over rows of 512. 128 threads/row, 4 elements per thread.
__global__ __launch_bounds__(128)
void softmax_kernel(float* __restrict__ s)
{
    float* p = s + (long long)blockIdx.x * SK;
    const int t = threadIdx.x;
    float v[4];
    float m = -1e30f;
    #pragma unroll
    for (int i = 0; i < 4; i++) { v[i] = p[t + i * 128]; m = fmaxf(m, v[i]); }
    m = warp_max(m);
    __shared__ float shm[4], shs[4];
    if ((t & 31) == 0) shm[t >> 5] = m;
    __syncthreads();
    m = fmaxf(fmaxf(shm[0], shm[1]), fmaxf(shm[2], shm[3]));
    float sum = 0.f;
    #pragma unroll
    for (int i = 0; i < 4; i++) { v[i] = __expf(v[i] - m); sum += v[i]; }
    sum = warp_sum(sum);
    if ((t & 31) == 0) shs[t >> 5] = sum;
    __syncthreads();
    const float inv = 1.0f / (shs[0] + shs[1] + shs[2] + shs[3]);
    #pragma unroll
    for (int i = 0; i < 4; i++) p[t + i * 128] = v[i] * inv;
}

// ---------------------------------------------------------------------------
// Launch
// ---------------------------------------------------------------------------
extern "C" void kernel_launch(void* const* d_in, const int* in_sizes, int n_in,
                              void* d_out, int out_size)
{
    const float* x   = (const float*)d_in[0];
    const float* ctx = (const float*)d_in[1];
    const float* Wq  = (const float*)d_in[2];
    const float* bq  = (const float*)d_in[3];
    const float* Wk  = (const float*)d_in[4];
    const float* bk  = (const float*)d_in[5];
    const float* Wv  = (const float*)d_in[6];
    const float* bv  = (const float*)d_in[7];
    const float* Wo  = (const float*)d_in[8];
    const float* bo  = (const float*)d_in[9];
    const float* gq  = (const float*)d_in[10];
    const float* gk  = (const float*)d_in[11];
    float* out = (float*)d_out;

    float *qbuf, *kbuf, *vbuf, *attn, *scores;
    cudaGetSymbolAddress((void**)&qbuf,   g_qbuf);
    cudaGetSymbolAddress((void**)&kbuf,   g_kbuf);
    cudaGetSymbolAddress((void**)&vbuf,   g_vbuf);
    cudaGetSymbolAddress((void**)&attn,   g_attn);
    cudaGetSymbolAddress((void**)&scores, g_scores);

    const float scale = 1.0f / sqrtf((float)HD);

    // 1) Q = x @ Wq + bq                      [8192,2048]
    gemm_tiled<false><<<dim3(DIMC / 128, LQ / 128, 1), 256>>>(
        x, Wq, bq, qbuf, LQ, DIMC, DIMC, DIMC, DIMC, DIMC, 1.0f, 0, 0, 0);
    // 2) K = ctx @ Wk + bk                    [512,2048]
    gemm_tiled<false><<<dim3(DIMC / 128, SK / 128, 1), 256>>>(
        ctx, Wk, bk, kbuf, SK, DIMC, CTXD, CTXD, DIMC, DIMC, 1.0f, 0, 0, 0);
    // 3) V = ctx @ Wv + bv                    [512,2048]
    gemm_tiled<false><<<dim3(DIMC / 128, SK / 128, 1), 256>>>(
        ctx, Wv, bv, vbuf, SK, DIMC, CTXD, CTXD, DIMC, DIMC, 1.0f, 0, 0, 0);
    // 4) RMSNorm(Q)*g_q, RMSNorm(K)*g_k (in place)
    rmsnorm_kernel<<<LQ, 256>>>(qbuf, gq);
    rmsnorm_kernel<<<SK, 256>>>(kbuf, gk);
    // 5) scores[h] = scale * Q_h @ K_h^T      per head: [8192,512], K-dim 128
    gemm_tiled<true><<<dim3(SK / 128, LQ / 128, NH), 256>>>(
        qbuf, kbuf, nullptr, scores, LQ, SK, HD, DIMC, DIMC, SK, scale,
        (long long)HD, (long long)HD, (long long)LQ * SK);
    // 6) softmax over last dim
    softmax_kernel<<<NH * LQ, 128>>>(scores);
    // 7) attn[:, h] = P_h @ V_h               per head: [8192,128], K-dim 512
    gemm_tiled<false><<<dim3(HD / 128, LQ / 128, NH), 256>>>(
        scores, vbuf, nullptr, attn, LQ, HD, SK, SK, DIMC, DIMC, 1.0f,
        (long long)LQ * SK, (long long)HD, (long long)HD);
    // 8) out = attn @ Wo + bo                 [8192,2048]
    gemm_tiled<false><<<dim3(DIMC / 128, LQ / 128, 1), 256>>>(
        attn, Wo, bo, out, LQ, DIMC, DIMC, DIMC, DIMC, DIMC, 1.0f, 0, 0, 0);
}

// round 3
// speedup vs baseline: 3.3093x; 3.3093x over previous
#include <cuda_runtime.h>
#include <cuda_fp16.h>
#include <cstdint>
#include <math.h>

#define DIMC 2048
#define CTXD 4096
#define NH   16
#define HD   128
#define LQ   8192
#define SK   512

// ---------------------------------------------------------------------------
// Scratch (__device__ globals — no runtime allocation)
// ---------------------------------------------------------------------------
__device__ __half g_xh[(size_t)LQ * DIMC],  g_xl[(size_t)LQ * DIMC];
__device__ __half g_ch[(size_t)SK * CTXD],  g_cl[(size_t)SK * CTXD];
__device__ __half g_wqt[(size_t)DIMC * DIMC];
__device__ __half g_wkvt[(size_t)2 * DIMC * CTXD];
__device__ __half g_wot[(size_t)DIMC * DIMC];
__device__ float  g_qbuf[(size_t)LQ * DIMC];
__device__ float  g_kvbuf[(size_t)SK * 2 * DIMC];
__device__ float  g_bkv[2 * DIMC];
__device__ __half g_qh[(size_t)LQ * DIMC], g_ql[(size_t)LQ * DIMC];
__device__ __half g_kh[(size_t)SK * DIMC];
__device__ __half g_vt[(size_t)DIMC * SK];
__device__ float  g_scores[(size_t)NH * LQ * SK];
__device__ __half g_ph[(size_t)NH * LQ * SK], g_pl[(size_t)NH * LQ * SK];
__device__ float  g_attn[(size_t)LQ * DIMC];
__device__ __half g_ah[(size_t)LQ * DIMC], g_al[(size_t)LQ * DIMC];

// ---------------------------------------------------------------------------
// PTX helpers (sm_80-era only: cp.async, ldmatrix, mma.sync — valid on sm_100)
// ---------------------------------------------------------------------------
__device__ __forceinline__ uint32_t smem_u32(const void* p) {
    uint32_t a;
    asm("{ .reg .u64 t; cvta.to.shared.u64 t, %1; cvt.u32.u64 %0, t; }" : "=r"(a) : "l"(p));
    return a;
}
#define CP_ASYNC16(d, s) asm volatile("cp.async.cg.shared.global [%0], [%1], 16;" :: "r"(d), "l"(s) : "memory")
#define CP_COMMIT()      asm volatile("cp.async.commit_group;" ::: "memory")

#define LDSM_X4(r, addr) \
    asm volatile("ldmatrix.sync.aligned.m8n8.x4.shared.b16 {%0,%1,%2,%3}, [%4];" \
        : "=r"((r)[0]), "=r"((r)[1]), "=r"((r)[2]), "=r"((r)[3]) : "r"(addr))

#define MMA16816(d, a, b0, b1) \
    asm volatile("mma.sync.aligned.m16n8k16.row.col.f32.f16.f16.f32 " \
        "{%0,%1,%2,%3}, {%4,%5,%6,%7}, {%8,%9}, {%0,%1,%2,%3};" \
        : "+f"((d)[0]), "+f"((d)[1]), "+f"((d)[2]), "+f"((d)[3]) \
        : "r"((a)[0]), "r"((a)[1]), "r"((a)[2]), "r"((a)[3]), "r"(b0), "r"(b1))

// ---------------------------------------------------------------------------
// GEMM via mma.sync, fp32 emulated as fp16 split on A (2 passes):
//   C = alpha * ((Ah + Al) @ Bh^T) + bias
//   A: [M,K] K-major fp16 hi/lo; B: [N,K] K-major fp16 (hi only).
//   BM=BN=128, BK=64, 4-stage cp.async pipeline, 8 warps (2x4), 64x32 warp tile.
// ---------------------------------------------------------------------------
__global__ void __launch_bounds__(256, 1)
gemm_mma_split(const __half* __restrict__ Ah, const __half* __restrict__ Al,
               const __half* __restrict__ Bh,
               const float* __restrict__ bias, float* __restrict__ C,
               int K, int lda, int ldb, int ldc, float alpha,
               long long aBatch, long long bBatch, long long cBatch)
{
    constexpr int BM = 128, BN = 128, BK = 64, S = 4;
    constexpr int ASZ = BM * BK * 2;          // 16 KB
    constexpr int STAGE = 2 * ASZ;            // 32 KB

    extern __shared__ char smem[];
    const uint32_t sb = smem_u32(smem);

    const int tid  = threadIdx.x;
    const int lane = tid & 31;
    const int wid  = tid >> 5;
    const int wm   = wid >> 2;                // 0..1  (M warp)
    const int wn   = wid & 3;                 // 0..3  (N warp)

    Ah += (long long)blockIdx.z * aBatch;
    Al += (long long)blockIdx.z * aBatch;
    Bh += (long long)blockIdx.z * bBatch;
    C  += (long long)blockIdx.z * cBatch;
    const int bm = blockIdx.y * BM;
    const int bn = blockIdx.x * BN;

    const int kchunks = K / BK;
    const int CT = 2 * kchunks;

    auto load_chunk = [&](int c) {
        const __half* Ap = (c >= kchunks) ? Al : Ah;
        const int kk = (c >= kchunks) ? c - kchunks : c;
        const uint32_t sbase = sb + (uint32_t)(c & (S - 1)) * STAGE;
        const long long k0 = (long long)kk * BK;
        #pragma unroll
        for (int i = 0; i < 4; i++) {
            int idx = tid + i * 256;
            int r = idx >> 3, j = idx & 7;
            uint32_t d = sbase + r * 128 + ((j ^ (r & 7)) * 16);
            CP_ASYNC16(d, Ap + (long long)(bm + r) * lda + k0 + j * 8);
        }
        #pragma unroll
        for (int i = 0; i < 4; i++) {
            int idx = tid + i * 256;
            int r = idx >> 3, j = idx & 7;
            uint32_t d = sbase + ASZ + r * 128 + ((j ^ (r & 7)) * 16);
            CP_ASYNC16(d, Bh + (long long)(bn + r) * ldb + k0 + j * 8);
        }
        CP_COMMIT();
    };

    float acc[4][4][4] = {};

    int issued = (S - 1 < CT) ? (S - 1) : CT;
    for (int c0 = 0; c0 < issued; c0++) load_chunk(c0);

    const int rlane = lane & 15;              // ldmatrix row within 16
    const int klane = lane >> 4;              // ldmatrix k-chunk select (0/1)
    const int ra = wm * 64 + rlane;           // A base row for this warp
    const int rb = wn * 32 + rlane;           // B base row for this warp

    for (int c = 0; c < CT; c++) {
        if (issued < CT) { load_chunk(issued); issued++; }
        const int pending = issued - (c + 1);
        if      (pending <= 0) asm volatile("cp.async.wait_group 0;" ::: "memory");
        else if (pending == 1) asm volatile("cp.async.wait_group 1;" ::: "memory");
        else if (pending == 2) asm volatile("cp.async.wait_group 2;" ::: "memory");
        else                   asm volatile("cp.async.wait_group 3;" ::: "memory");
        __syncthreads();

        const uint32_t base = sb + (uint32_t)(c & (S - 1)) * STAGE;
        #pragma unroll
        for (int ks = 0; ks < 4; ks++) {
            const int jA = 2 * ks + klane;
            uint32_t a[4][4];
            #pragma unroll
            for (int mt = 0; mt < 4; mt++) {
                int r = ra + mt * 16;
                uint32_t addr = base + r * 128 + ((jA ^ (r & 7)) * 16);
                LDSM_X4(a[mt], addr);
            }
            uint32_t b[2][4];
            #pragma unroll
            for (int h = 0; h < 2; h++) {
                int r = rb + h * 16;
                uint32_t addr = base + ASZ + r * 128 + ((jA ^ (r & 7)) * 16);
                LDSM_X4(b[h], addr);
            }
            #pragma unroll
            for (int mt = 0; mt < 4; mt++)
                #pragma unroll
                for (int nt = 0; nt < 4; nt++)
                    MMA16816(acc[mt][nt], a[mt], b[nt >> 1][nt & 1], b[nt >> 1][(nt & 1) + 2]);
        }
        __syncthreads();
    }

    // epilogue
    const int row0 = bm + wm * 64;
    const int col0 = bn + wn * 32;
    const int tr = lane >> 2;
    const int tc = (lane & 3) * 2;
    #pragma unroll
    for (int mt = 0; mt < 4; mt++) {
        #pragma unroll
        for (int nt = 0; nt < 4; nt++) {
            const int cc = col0 + nt * 8 + tc;
            float bx = 0.f, by = 0.f;
            if (bias) { bx = bias[cc]; by = bias[cc + 1]; }
            {
                const long long r = row0 + mt * 16 + tr;
                float2 v = { acc[mt][nt][0] * alpha + bx, acc[mt][nt][1] * alpha + by };
                *(float2*)&C[r * ldc + cc] = v;
            }
            {
                const long long r = row0 + mt * 16 + tr + 8;
                float2 v = { acc[mt][nt][2] * alpha + bx, acc[mt][nt][3] * alpha + by };
                *(float2*)&C[r * ldc + cc] = v;
            }
        }
    }
}

// ---------------------------------------------------------------------------
// Elementwise / transform kernels
// ---------------------------------------------------------------------------
__device__ __forceinline__ void split1h(float v, __half& h, __half& l) {
    h = __float2half_rn(v);
    l = __float2half_rn(v - __half2float(h));
}

__global__ __launch_bounds__(256) void split4h_kernel(const float* __restrict__ in,
                                                      __half* __restrict__ oh,
                                                      __half* __restrict__ ol) {
    const long long i = ((long long)blockIdx.x * 256 + threadIdx.x) * 4;
    float4 v = *(const float4*)&in[i];
    __half h[4], l[4];
    split1h(v.x, h[0], l[0]); split1h(v.y, h[1], l[1]);
    split1h(v.z, h[2], l[2]); split1h(v.w, h[3], l[3]);
    *(uint2*)&oh[i] = *(uint2*)h;
    *(uint2*)&ol[i] = *(uint2*)l;
}

// in[R][Cc] fp32 (row stride inLd) -> out[Cc][R] fp16 (hi only)
__global__ __launch_bounds__(256) void round_transpose_kernel(
    const float* __restrict__ in, __half* __restrict__ o, int R, int Cc, int inLd)
{
    __shared__ float t[32][33];
    const int c0 = blockIdx.x * 32, r0 = blockIdx.y * 32;
    const int tx = threadIdx.x & 31, ty = threadIdx.x >> 5;
    #pragma unroll
    for (int i = 0; i < 4; i++)
        t[ty + 8 * i][tx] = in[(long long)(r0 + ty + 8 * i) * inLd + c0 + tx];
    __syncthreads();
    #pragma unroll
    for (int i = 0; i < 4; i++)
        o[(long long)(c0 + ty + 8 * i) * R + r0 + tx] = __float2half_rn(t[tx][ty + 8 * i]);
}

__device__ __forceinline__ float warp_sum(float v) {
    #pragma unroll
    for (int o = 16; o > 0; o >>= 1) v += __shfl_xor_sync(0xffffffffu, v, o);
    return v;
}
__device__ __forceinline__ float warp_max(float v) {
    #pragma unroll
    for (int o = 16; o > 0; o >>= 1) v = fmaxf(v, __shfl_xor_sync(0xffffffffu, v, o));
    return v;
}

// RMSNorm over first DIMC cols of row (row stride ld); fp16 hi (+ optional lo) out
__global__ __launch_bounds__(256) void rmsnorm_split_kernel(
    const float* __restrict__ in, const float* __restrict__ g,
    __half* __restrict__ oh, __half* __restrict__ ol, int ld)
{
    const float* p = in + (long long)blockIdx.x * ld;
    const int t = threadIdx.x;
    float v[8]; float ss = 0.f;
    #pragma unroll
    for (int i = 0; i < 8; i++) { v[i] = p[t + i * 256]; ss += v[i] * v[i]; }
    ss = warp_sum(ss);
    __shared__ float sh[8];
    if ((t & 31) == 0) sh[t >> 5] = ss;
    __syncthreads();
    float tot = 0.f;
    #pragma unroll
    for (int i = 0; i < 8; i++) tot += sh[i];
    const float inv = rsqrtf(tot * (1.0f / DIMC) + 1e-6f);
    const long long ob = (long long)blockIdx.x * DIMC;
    #pragma unroll
    for (int i = 0; i < 8; i++) {
        float y = v[i] * inv * g[t + i * 256];
        __half h, l; split1h(y, h, l);
        oh[ob + t + i * 256] = h;
        if (ol) ol[ob + t + i * 256] = l;
    }
}

__global__ __launch_bounds__(128) void softmax_split_kernel(
    const float* __restrict__ s, __half* __restrict__ oh, __half* __restrict__ ol)
{
    const float* p = s + (long long)blockIdx.x * SK;
    const int t = threadIdx.x;
    float v[4]; float m = -1e30f;
    #pragma unroll
    for (int i = 0; i < 4; i++) { v[i] = p[t + i * 128]; m = fmaxf(m, v[i]); }
    m = warp_max(m);
    __shared__ float shm[4], shs[4];
    if ((t & 31) == 0) shm[t >> 5] = m;
    __syncthreads();
    m = fmaxf(fmaxf(shm[0], shm[1]), fmaxf(shm[2], shm[3]));
    float sum = 0.f;
    #pragma unroll
    for (int i = 0; i < 4; i++) { v[i] = __expf(v[i] - m); sum += v[i]; }
    sum = warp_sum(sum);
    if ((t & 31) == 0) shs[t >> 5] = sum;
    __syncthreads();
    const float inv = 1.0f / (shs[0] + shs[1] + shs[2] + shs[3]);
    const long long ob = (long long)blockIdx.x * SK;
    #pragma unroll
    for (int i = 0; i < 4; i++) {
        __half h, l; split1h(v[i] * inv, h, l);
        oh[ob + t + i * 128] = h;
        ol[ob + t + i * 128] = l;
    }
}

__global__ void concat_bias_kernel(const float* __restrict__ a,
                                   const float* __restrict__ b,
                                   float* __restrict__ o) {
    int i = blockIdx.x * 256 + threadIdx.x;
    if (i < 2 * DIMC) o[i] = (i < DIMC) ? a[i] : b[i - DIMC];
}

// ---------------------------------------------------------------------------
// Launch
// ---------------------------------------------------------------------------
#define SMEM_GEMM (4 * 32768)

extern "C" void kernel_launch(void* const* d_in, const int* in_sizes, int n_in,
                              void* d_out, int out_size)
{
    const float* x   = (const float*)d_in[0];
    const float* ctx = (const float*)d_in[1];
    const float* Wq  = (const float*)d_in[2];
    const float* bq  = (const float*)d_in[3];
    const float* Wk  = (const float*)d_in[4];
    const float* bk  = (const float*)d_in[5];
    const float* Wv  = (const float*)d_in[6];
    const float* bv  = (const float*)d_in[7];
    const float* Wo  = (const float*)d_in[8];
    const float* bo  = (const float*)d_in[9];
    const float* gq  = (const float*)d_in[10];
    const float* gk  = (const float*)d_in[11];
    float* out = (float*)d_out;

    __half *xh, *xl, *ch, *cl, *wqt, *wkvt, *wot, *qh, *ql, *kh, *vt, *ph, *pl, *ah, *al;
    float *qbuf, *kvbuf, *bkv, *scores, *attn;
    cudaGetSymbolAddress((void**)&xh, g_xh);     cudaGetSymbolAddress((void**)&xl, g_xl);
    cudaGetSymbolAddress((void**)&ch, g_ch);     cudaGetSymbolAddress((void**)&cl, g_cl);
    cudaGetSymbolAddress((void**)&wqt, g_wqt);   cudaGetSymbolAddress((void**)&wkvt, g_wkvt);
    cudaGetSymbolAddress((void**)&wot, g_wot);
    cudaGetSymbolAddress((void**)&qbuf, g_qbuf); cudaGetSymbolAddress((void**)&kvbuf, g_kvbuf);
    cudaGetSymbolAddress((void**)&bkv, g_bkv);
    cudaGetSymbolAddress((void**)&qh, g_qh);     cudaGetSymbolAddress((void**)&ql, g_ql);
    cudaGetSymbolAddress((void**)&kh, g_kh);     cudaGetSymbolAddress((void**)&vt, g_vt);
    cudaGetSymbolAddress((void**)&scores, g_scores);
    cudaGetSymbolAddress((void**)&ph, g_ph);     cudaGetSymbolAddress((void**)&pl, g_pl);
    cudaGetSymbolAddress((void**)&attn, g_attn);
    cudaGetSymbolAddress((void**)&ah, g_ah);     cudaGetSymbolAddress((void**)&al, g_al);

    cudaFuncSetAttribute(gemm_mma_split, cudaFuncAttributeMaxDynamicSharedMemorySize, SMEM_GEMM);

    const float scale = 1.0f / sqrtf((float)HD);

    // -- operand prep
    split4h_kernel<<<(LQ * DIMC) / 1024, 256>>>(x, xh, xl);
    split4h_kernel<<<(SK * CTXD) / 1024, 256>>>(ctx, ch, cl);
    round_transpose_kernel<<<dim3(DIMC / 32, DIMC / 32), 256>>>(Wq, wqt, DIMC, DIMC, DIMC);
    round_transpose_kernel<<<dim3(DIMC / 32, CTXD / 32), 256>>>(Wk, wkvt, CTXD, DIMC, DIMC);
    round_transpose_kernel<<<dim3(DIMC / 32, CTXD / 32), 256>>>(
        Wv, wkvt + (size_t)DIMC * CTXD, CTXD, DIMC, DIMC);
    round_transpose_kernel<<<dim3(DIMC / 32, DIMC / 32), 256>>>(Wo, wot, DIMC, DIMC, DIMC);
    concat_bias_kernel<<<(2 * DIMC) / 256, 256>>>(bk, bv, bkv);

    // -- Q projection: qbuf = x @ Wq + bq     [8192, 2048]
    gemm_mma_split<<<dim3(DIMC / 128, LQ / 128, 1), 256, SMEM_GEMM>>>(
        xh, xl, wqt, bq, qbuf, DIMC, DIMC, DIMC, DIMC, 1.0f, 0, 0, 0);
    // -- KV projection (merged): kvbuf = ctx @ [Wk|Wv] + [bk|bv]   [512, 4096]
    gemm_mma_split<<<dim3((2 * DIMC) / 128, SK / 128, 1), 256, SMEM_GEMM>>>(
        ch, cl, wkvt, bkv, kvbuf, CTXD, CTXD, CTXD, 2 * DIMC, 1.0f, 0, 0, 0);

    // -- RMSNorm: Q -> hi+lo, K -> hi only
    rmsnorm_split_kernel<<<LQ, 256>>>(qbuf, gq, qh, ql, DIMC);
    rmsnorm_split_kernel<<<SK, 256>>>(kvbuf, gk, kh, nullptr, 2 * DIMC);
    // -- V transpose -> vt[h*128+d][s]  (fp16 hi)
    round_transpose_kernel<<<dim3(DIMC / 32, SK / 32), 256>>>(
        kvbuf + DIMC, vt, SK, DIMC, 2 * DIMC);

    // -- scores = scale * Q_h @ K_h^T  (per head, K-dim 128)
    gemm_mma_split<<<dim3(SK / 128, LQ / 128, NH), 256, SMEM_GEMM>>>(
        qh, ql, kh, nullptr, scores, HD, DIMC, DIMC, SK, scale,
        (long long)HD, (long long)HD, (long long)LQ * SK);
    // -- softmax + split
    softmax_split_kernel<<<NH * LQ, 128>>>(scores, ph, pl);
    // -- attn = P_h @ V_h  (per head, K-dim 512; V pre-transposed)
    gemm_mma_split<<<dim3(HD / 128, LQ / 128, NH), 256, SMEM_GEMM>>>(
        ph, pl, vt, nullptr, attn, SK, SK, SK, DIMC, 1.0f,
        (long long)LQ * SK, (long long)HD * SK, (long long)HD);
    // -- split attn, O projection
    split4h_kernel<<<(LQ * DIMC) / 1024, 256>>>(attn, ah, al);
    gemm_mma_split<<<dim3(DIMC / 128, LQ / 128, 1), 256, SMEM_GEMM>>>(
        ah, al, wot, bo, out, DIMC, DIMC, DIMC, DIMC, 1.0f, 0, 0, 0);
}

// round 5
// speedup vs baseline: 3.5925x; 1.0856x over previous
#include <cuda_runtime.h>
#include <cuda_fp16.h>
#include <cstdint>
#include <math.h>

#define DIMC 2048
#define CTXD 4096
#define NH   16
#define HD   128
#define LQ   8192
#define SK   512

// ---------------------------------------------------------------------------
// Scratch (__device__ globals — no runtime allocation)
// ---------------------------------------------------------------------------
__device__ __half g_xh[(size_t)LQ * DIMC],  g_xl[(size_t)LQ * DIMC];
__device__ __half g_ch[(size_t)SK * CTXD],  g_cl[(size_t)SK * CTXD];
__device__ __half g_wqt[(size_t)DIMC * DIMC];
__device__ __half g_wkvt[(size_t)2 * DIMC * CTXD];
__device__ __half g_wot[(size_t)DIMC * DIMC];
__device__ float  g_qbuf[(size_t)LQ * DIMC];
__device__ float  g_kvbuf[(size_t)SK * 2 * DIMC];
__device__ float  g_bkv[2 * DIMC];
__device__ __half g_qh[(size_t)LQ * DIMC], g_ql[(size_t)LQ * DIMC];
__device__ __half g_kh[(size_t)SK * DIMC];
__device__ __half g_vt[(size_t)DIMC * SK];
__device__ __half g_ah[(size_t)LQ * DIMC], g_al[(size_t)LQ * DIMC];

// ---------------------------------------------------------------------------
// PTX helpers (sm_80-era: cp.async, ldmatrix, mma.sync — valid on base sm_100)
// ---------------------------------------------------------------------------
__device__ __forceinline__ uint32_t smem_u32(const void* p) {
    uint32_t a;
    asm("{ .reg .u64 t; cvta.to.shared.u64 t, %1; cvt.u32.u64 %0, t; }" : "=r"(a) : "l"(p));
    return a;
}
#define CP_ASYNC16(d, s) asm volatile("cp.async.cg.shared.global [%0], [%1], 16;" :: "r"(d), "l"(s) : "memory")
#define CP_COMMIT()      asm volatile("cp.async.commit_group;" ::: "memory")

#define LDSM_X4(r, addr) \
    asm volatile("ldmatrix.sync.aligned.m8n8.x4.shared.b16 {%0,%1,%2,%3}, [%4];" \
        : "=r"((r)[0]), "=r"((r)[1]), "=r"((r)[2]), "=r"((r)[3]) : "r"(addr))

#define MMA16816(d, a, b0, b1) \
    asm volatile("mma.sync.aligned.m16n8k16.row.col.f32.f16.f16.f32 " \
        "{%0,%1,%2,%3}, {%4,%5,%6,%7}, {%8,%9}, {%0,%1,%2,%3};" \
        : "+f"((d)[0]), "+f"((d)[1]), "+f"((d)[2]), "+f"((d)[3]) \
        : "r"((a)[0]), "r"((a)[1]), "r"((a)[2]), "r"((a)[3]), "r"(b0), "r"(b1))

__device__ __forceinline__ uint32_t packh2(float a, float b) {
    __half2 h = __floats2half2_rn(a, b);
    return *reinterpret_cast<uint32_t*>(&h);
}
__device__ __forceinline__ uint32_t pack_hi_res(float a, float b, float& ra, float& rb) {
    __half ha = __float2half_rn(a), hb = __float2half_rn(b);
    ra = a - __half2float(ha);
    rb = b - __half2float(hb);
    __half2 h2 = __halves2half2(ha, hb);
    return *reinterpret_cast<uint32_t*>(&h2);
}

// ---------------------------------------------------------------------------
// GEMM via mma.sync, fp32 emulated as fp16 split on A (2 passes):
//   C = alpha * ((Ah + Al) @ Bh^T) + bias
// ---------------------------------------------------------------------------
__global__ void __launch_bounds__(256, 1)
gemm_mma_split(const __half* __restrict__ Ah, const __half* __restrict__ Al,
               const __half* __restrict__ Bh,
               const float* __restrict__ bias, float* __restrict__ C,
               int K, int lda, int ldb, int ldc, float alpha,
               long long aBatch, long long bBatch, long long cBatch)
{
    constexpr int BM = 128, BN = 128, BK = 64, S = 4;
    constexpr int ASZ = BM * BK * 2;
    constexpr int STAGE = 2 * ASZ;

    extern __shared__ char smem[];
    const uint32_t sb = smem_u32(smem);

    const int tid  = threadIdx.x;
    const int lane = tid & 31;
    const int wid  = tid >> 5;
    const int wm   = wid >> 2;
    const int wn   = wid & 3;

    Ah += (long long)blockIdx.z * aBatch;
    Al += (long long)blockIdx.z * aBatch;
    Bh += (long long)blockIdx.z * bBatch;
    C  += (long long)blockIdx.z * cBatch;
    const int bm = blockIdx.y * BM;
    const int bn = blockIdx.x * BN;

    const int kchunks = K / BK;
    const int CT = 2 * kchunks;

    auto load_chunk = [&](int c) {
        const __half* Ap = (c >= kchunks) ? Al : Ah;
        const int kk = (c >= kchunks) ? c - kchunks : c;
        const uint32_t sbase = sb + (uint32_t)(c & (S - 1)) * STAGE;
        const long long k0 = (long long)kk * BK;
        #pragma unroll
        for (int i = 0; i < 4; i++) {
            int idx = tid + i * 256;
            int r = idx >> 3, j = idx & 7;
            uint32_t d = sbase + r * 128 + ((j ^ (r & 7)) * 16);
            CP_ASYNC16(d, Ap + (long long)(bm + r) * lda + k0 + j * 8);
        }
        #pragma unroll
        for (int i = 0; i < 4; i++) {
            int idx = tid + i * 256;
            int r = idx >> 3, j = idx & 7;
            uint32_t d = sbase + ASZ + r * 128 + ((j ^ (r & 7)) * 16);
            CP_ASYNC16(d, Bh + (long long)(bn + r) * ldb + k0 + j * 8);
        }
        CP_COMMIT();
    };

    float acc[4][4][4] = {};

    int issued = (S - 1 < CT) ? (S - 1) : CT;
    for (int c0 = 0; c0 < issued; c0++) load_chunk(c0);

    const int rlane = lane & 15;
    const int klane = lane >> 4;
    const int ra = wm * 64 + rlane;
    const int rb = wn * 32 + rlane;

    for (int c = 0; c < CT; c++) {
        if (issued < CT) { load_chunk(issued); issued++; }
        const int pending = issued - (c + 1);
        if      (pending <= 0) asm volatile("cp.async.wait_group 0;" ::: "memory");
        else if (pending == 1) asm volatile("cp.async.wait_group 1;" ::: "memory");
        else if (pending == 2) asm volatile("cp.async.wait_group 2;" ::: "memory");
        else                   asm volatile("cp.async.wait_group 3;" ::: "memory");
        __syncthreads();

        const uint32_t base = sb + (uint32_t)(c & (S - 1)) * STAGE;
        #pragma unroll
        for (int ks = 0; ks < 4; ks++) {
            const int jA = 2 * ks + klane;
            uint32_t a[4][4];
            #pragma unroll
            for (int mt = 0; mt < 4; mt++) {
                int r = ra + mt * 16;
                uint32_t addr = base + r * 128 + ((jA ^ (r & 7)) * 16);
                LDSM_X4(a[mt], addr);
            }
            uint32_t b[2][4];
            #pragma unroll
            for (int h = 0; h < 2; h++) {
                int r = rb + h * 16;
                uint32_t addr = base + ASZ + r * 128 + ((jA ^ (r & 7)) * 16);
                LDSM_X4(b[h], addr);
            }
            #pragma unroll
            for (int mt = 0; mt < 4; mt++)
                #pragma unroll
                for (int nt = 0; nt < 4; nt++)
                    MMA16816(acc[mt][nt], a[mt], b[nt >> 1][nt & 1], b[nt >> 1][(nt & 1) + 2]);
        }
        __syncthreads();
    }

    const int row0 = bm + wm * 64;
    const int col0 = bn + wn * 32;
    const int tr = lane >> 2;
    const int tc = (lane & 3) * 2;
    #pragma unroll
    for (int mt = 0; mt < 4; mt++) {
        #pragma unroll
        for (int nt = 0; nt < 4; nt++) {
            const int cc = col0 + nt * 8 + tc;
            float bx = 0.f, by = 0.f;
            if (bias) { bx = bias[cc]; by = bias[cc + 1]; }
            {
                const long long r = row0 + mt * 16 + tr;
                float2 v = { acc[mt][nt][0] * alpha + bx, acc[mt][nt][1] * alpha + by };
                *(float2*)&C[r * ldc + cc] = v;
            }
            {
                const long long r = row0 + mt * 16 + tr + 8;
                float2 v = { acc[mt][nt][2] * alpha + bx, acc[mt][nt][3] * alpha + by };
                *(float2*)&C[r * ldc + cc] = v;
            }
        }
    }
}

// ---------------------------------------------------------------------------
// Fused flash attention: per (head, 128-row Q tile) CTA.
//   scores = (Qh+Ql) @ K^T  (Q pre-scaled by 1/sqrt(HD) in rmsnorm)
//   online softmax over S=512 in 4 chunks of 128
//   O += (Phi + Plo) @ V    (P split register-side)
//   epilogue writes fp16 hi/lo of O directly (input to O projection).
// 8 warps; warp w owns output rows 16w..16w+15 (full rows -> warp-local softmax).
// ---------------------------------------------------------------------------
__global__ void __launch_bounds__(256, 1)
flash_attn_kernel(const __half* __restrict__ qh, const __half* __restrict__ ql,
                  const __half* __restrict__ kh, const __half* __restrict__ vt,
                  __half* __restrict__ oh, __half* __restrict__ ol)
{
    constexpr int TILE = 16384;               // one 128x64 fp16 slab
    extern __shared__ char smem[];
    const uint32_t sb = smem_u32(smem);
    const uint32_t QHS = sb;                  // 2 slabs (32KB)
    const uint32_t QLS = sb + 32768;          // 2 slabs (32KB)
    const uint32_t ST0 = sb + 65536;          // stage: K(32KB)+V(32KB), x2 stages

    const int tid = threadIdx.x, lane = tid & 31, wid = tid >> 5;
    const int h  = blockIdx.x;
    const int bm = blockIdx.y * 128;
    const int rlane = lane & 15, klane = lane >> 4;
    const int tr = lane >> 2, tc2 = (lane & 3) * 2;

    const __half* qhp = qh + (size_t)bm * DIMC + h * HD;
    const __half* qlp = ql + (size_t)bm * DIMC + h * HD;
    const __half* khp = kh + h * HD;
    const __half* vtp = vt + (size_t)h * HD * SK;

    auto load128 = [&](uint32_t dstbase, const __half* src, int ld) {
        #pragma unroll
        for (int i = 0; i < 8; i++) {
            int idx = tid + i * 256;
            int slab = idx >> 10, rem = idx & 1023;
            int r = rem >> 3, j = rem & 7;
            uint32_t d = dstbase + slab * TILE + r * 128 + ((j ^ (r & 7)) * 16);
            CP_ASYNC16(d, src + (long long)r * ld + slab * 64 + j * 8);
        }
    };

    // prologue: Q (group 0), KV chunk0 (group 1), KV chunk1 (group 2)
    load128(QHS, qhp, DIMC);
    load128(QLS, qlp, DIMC);
    CP_COMMIT();
    load128(ST0,          khp,             DIMC);
    load128(ST0 + 32768,  vtp,             SK);
    CP_COMMIT();
    load128(ST0 + 65536,          khp + 128 * DIMC, DIMC);
    load128(ST0 + 65536 + 32768,  vtp + 128,        SK);
    CP_COMMIT();

    float oacc[16][4] = {};
    float m0 = -INFINITY, m1 = -INFINITY, l0 = 0.f, l1 = 0.f;
    const int ra = 16 * wid + rlane;

    #pragma unroll
    for (int c = 0; c < 4; c++) {
        if (c < 3) asm volatile("cp.async.wait_group 1;" ::: "memory");
        else       asm volatile("cp.async.wait_group 0;" ::: "memory");
        __syncthreads();
        const uint32_t kb = ST0 + (uint32_t)(c & 1) * 65536;
        const uint32_t vb = kb + 32768;

        // ---- S = (Qh + Ql) @ K^T  (pre-scaled) ----
        float sacc[16][4] = {};
        #pragma unroll
        for (int slab = 0; slab < 2; slab++) {
            #pragma unroll
            for (int ks = 0; ks < 4; ks++) {
                const int jA = 2 * ks + klane;
                uint32_t bfr[8][4];
                #pragma unroll
                for (int bt = 0; bt < 8; bt++) {
                    int rb = 16 * bt + rlane;
                    LDSM_X4(bfr[bt], kb + slab * TILE + rb * 128 + ((jA ^ (rb & 7)) * 16));
                }
                uint32_t a[4];
                LDSM_X4(a, QHS + slab * TILE + ra * 128 + ((jA ^ (ra & 7)) * 16));
                #pragma unroll
                for (int bt = 0; bt < 8; bt++) {
                    MMA16816(sacc[2 * bt],     a, bfr[bt][0], bfr[bt][2]);
                    MMA16816(sacc[2 * bt + 1], a, bfr[bt][1], bfr[bt][3]);
                }
                LDSM_X4(a, QLS + slab * TILE + ra * 128 + ((jA ^ (ra & 7)) * 16));
                #pragma unroll
                for (int bt = 0; bt < 8; bt++) {
                    MMA16816(sacc[2 * bt],     a, bfr[bt][0], bfr[bt][2]);
                    MMA16816(sacc[2 * bt + 1], a, bfr[bt][1], bfr[bt][3]);
                }
            }
        }

        // ---- online softmax ----
        float cm0 = -INFINITY, cm1 = -INFINITY;
        #pragma unroll
        for (int nt = 0; nt < 16; nt++) {
            cm0 = fmaxf(cm0, fmaxf(sacc[nt][0], sacc[nt][1]));
            cm1 = fmaxf(cm1, fmaxf(sacc[nt][2], sacc[nt][3]));
        }
        cm0 = fmaxf(cm0, __shfl_xor_sync(0xffffffffu, cm0, 1));
        cm0 = fmaxf(cm0, __shfl_xor_sync(0xffffffffu, cm0, 2));
        cm1 = fmaxf(cm1, __shfl_xor_sync(0xffffffffu, cm1, 1));
        cm1 = fmaxf(cm1, __shfl_xor_sync(0xffffffffu, cm1, 2));
        const float mn0 = fmaxf(m0, cm0), mn1 = fmaxf(m1, cm1);
        const float co0 = __expf(m0 - mn0), co1 = __expf(m1 - mn1);
        m0 = mn0; m1 = mn1;
        float rs0 = 0.f, rs1 = 0.f;
        #pragma unroll
        for (int nt = 0; nt < 16; nt++) {
            sacc[nt][0] = __expf(sacc[nt][0] - mn0);
            sacc[nt][1] = __expf(sacc[nt][1] - mn0);
            sacc[nt][2] = __expf(sacc[nt][2] - mn1);
            sacc[nt][3] = __expf(sacc[nt][3] - mn1);
            rs0 += sacc[nt][0] + sacc[nt][1];
            rs1 += sacc[nt][2] + sacc[nt][3];
        }
        rs0 += __shfl_xor_sync(0xffffffffu, rs0, 1);
        rs0 += __shfl_xor_sync(0xffffffffu, rs0, 2);
        rs1 += __shfl_xor_sync(0xffffffffu, rs1, 1);
        rs1 += __shfl_xor_sync(0xffffffffu, rs1, 2);
        l0 = l0 * co0 + rs0;
        l1 = l1 * co1 + rs1;
        #pragma unroll
        for (int nt = 0; nt < 16; nt++) {
            oacc[nt][0] *= co0; oacc[nt][1] *= co0;
            oacc[nt][2] *= co1; oacc[nt][3] *= co1;
        }

        // ---- O += (Phi + Plo) @ V ----
        #pragma unroll
        for (int kt = 0; kt < 8; kt++) {
            const int slab = kt >> 2;
            const int jA = 2 * (kt & 3) + klane;
            uint32_t bfr[8][4];
            #pragma unroll
            for (int bt = 0; bt < 8; bt++) {
                int rb = 16 * bt + rlane;
                LDSM_X4(bfr[bt], vb + slab * TILE + rb * 128 + ((jA ^ (rb & 7)) * 16));
            }
            float r0, r1, r2, r3, r4, r5, r6, r7;
            uint32_t a[4];
            a[0] = pack_hi_res(sacc[2 * kt][0],     sacc[2 * kt][1],     r0, r1);
            a[1] = pack_hi_res(sacc[2 * kt][2],     sacc[2 * kt][3],     r2, r3);
            a[2] = pack_hi_res(sacc[2 * kt + 1][0], sacc[2 * kt + 1][1], r4, r5);
            a[3] = pack_hi_res(sacc[2 * kt + 1][2], sacc[2 * kt + 1][3], r6, r7);
            #pragma unroll
            for (int bt = 0; bt < 8; bt++) {
                MMA16816(oacc[2 * bt],     a, bfr[bt][0], bfr[bt][2]);
                MMA16816(oacc[2 * bt + 1], a, bfr[bt][1], bfr[bt][3]);
            }
            a[0] = packh2(r0, r1);
            a[1] = packh2(r2, r3);
            a[2] = packh2(r4, r5);
            a[3] = packh2(r6, r7);
            #pragma unroll
            for (int bt = 0; bt < 8; bt++) {
                MMA16816(oacc[2 * bt],     a, bfr[bt][0], bfr[bt][2]);
                MMA16816(oacc[2 * bt + 1], a, bfr[bt][1], bfr[bt][3]);
            }
        }
        __syncthreads();

        // prefetch chunk c+2 into the buffer just freed
        if (c < 2) {
            load128(kb, khp + (long long)(c + 2) * 128 * DIMC, DIMC);
            load128(vb, vtp + (c + 2) * 128, SK);
            CP_COMMIT();
        }
    }

    // ---- epilogue: divide by l, split fp16 hi/lo, store ----
    const float i0 = 1.0f / l0, i1 = 1.0f / l1;
    const long long rowA = bm + 16 * wid + tr;
    #pragma unroll
    for (int nt = 0; nt < 16; nt++) {
        const int col = h * HD + nt * 8 + tc2;
        {
            float y0 = oacc[nt][0] * i0, y1 = oacc[nt][1] * i0;
            float q0, q1;
            uint32_t hi = pack_hi_res(y0, y1, q0, q1);
            uint32_t lo = packh2(q0, q1);
            *(uint32_t*)&oh[rowA * DIMC + col] = hi;
            *(uint32_t*)&ol[rowA * DIMC + col] = lo;
        }
        {
            float y2 = oacc[nt][2] * i1, y3 = oacc[nt][3] * i1;
            float q2, q3;
            uint32_t hi = pack_hi_res(y2, y3, q2, q3);
            uint32_t lo = packh2(q2, q3);
            *(uint32_t*)&oh[(rowA + 8) * DIMC + col] = hi;
            *(uint32_t*)&ol[(rowA + 8) * DIMC + col] = lo;
        }
    }
}

// ---------------------------------------------------------------------------
// Elementwise / transform kernels
// ---------------------------------------------------------------------------
__device__ __forceinline__ void split1h(float v, __half& h, __half& l) {
    h = __float2half_rn(v);
    l = __float2half_rn(v - __half2float(h));
}

__global__ __launch_bounds__(256) void split4h_kernel(const float* __restrict__ in,
                                                      __half* __restrict__ oh,
                                                      __half* __restrict__ ol) {
    const long long i = ((long long)blockIdx.x * 256 + threadIdx.x) * 4;
    float4 v = *(const float4*)&in[i];
    __half h[4], l[4];
    split1h(v.x, h[0], l[0]); split1h(v.y, h[1], l[1]);
    split1h(v.z, h[2], l[2]); split1h(v.w, h[3], l[3]);
    *(uint2*)&oh[i] = *(uint2*)h;
    *(uint2*)&ol[i] = *(uint2*)l;
}

__global__ __launch_bounds__(256) void round_transpose_kernel(
    const float* __restrict__ in, __half* __restrict__ o, int R, int Cc, int inLd)
{
    __shared__ float t[32][33];
    const int c0 = blockIdx.x * 32, r0 = blockIdx.y * 32;
    const int tx = threadIdx.x & 31, ty = threadIdx.x >> 5;
    #pragma unroll
    for (int i = 0; i < 4; i++)
        t[ty + 8 * i][tx] = in[(long long)(r0 + ty + 8 * i) * inLd + c0 + tx];
    __syncthreads();
    #pragma unroll
    for (int i = 0; i < 4; i++)
        o[(long long)(c0 + ty + 8 * i) * R + r0 + tx] = __float2half_rn(t[tx][ty + 8 * i]);
}

__device__ __forceinline__ float warp_sum(float v) {
    #pragma unroll
    for (int o = 16; o > 0; o >>= 1) v += __shfl_xor_sync(0xffffffffu, v, o);
    return v;
}

// RMSNorm over first DIMC cols (row stride ld); out = alpha * norm; fp16 hi (+lo)
__global__ __launch_bounds__(256) void rmsnorm_split_kernel(
    const float* __restrict__ in, const float* __restrict__ g,
    __half* __restrict__ oh, __half* __restrict__ ol, int ld, float alpha)
{
    const float* p = in + (long long)blockIdx.x * ld;
    const int t = threadIdx.x;
    float v[8]; float ss = 0.f;
    #pragma unroll
    for (int i = 0; i < 8; i++) { v[i] = p[t + i * 256]; ss += v[i] * v[i]; }
    ss = warp_sum(ss);
    __shared__ float sh[8];
    if ((t & 31) == 0) sh[t >> 5] = ss;
    __syncthreads();
    float tot = 0.f;
    #pragma unroll
    for (int i = 0; i < 8; i++) tot += sh[i];
    const float inv = rsqrtf(tot * (1.0f / DIMC) + 1e-6f) * alpha;
    const long long ob = (long long)blockIdx.x * DIMC;
    #pragma unroll
    for (int i = 0; i < 8; i++) {
        float y = v[i] * inv * g[t + i * 256];
        __half h, l; split1h(y, h, l);
        oh[ob + t + i * 256] = h;
        if (ol) ol[ob + t + i * 256] = l;
    }
}

__global__ void concat_bias_kernel(const float* __restrict__ a,
                                   const float* __restrict__ b,
                                   float* __restrict__ o) {
    int i = blockIdx.x * 256 + threadIdx.x;
    if (i < 2 * DIMC) o[i] = (i < DIMC) ? a[i] : b[i - DIMC];
}

// ---------------------------------------------------------------------------
// Launch
// ---------------------------------------------------------------------------
#define SMEM_GEMM  (4 * 32768)
#define SMEM_FLASH (65536 + 2 * 65536)

extern "C" void kernel_launch(void* const* d_in, const int* in_sizes, int n_in,
                              void* d_out, int out_size)
{
    const float* x   = (const float*)d_in[0];
    const float* ctx = (const float*)d_in[1];
    const float* Wq  = (const float*)d_in[2];
    const float* bq  = (const float*)d_in[3];
    const float* Wk  = (const float*)d_in[4];
    const float* bk  = (const float*)d_in[5];
    const float* Wv  = (const float*)d_in[6];
    const float* bv  = (const float*)d_in[7];
    const float* Wo  = (const float*)d_in[8];
    const float* bo  = (const float*)d_in[9];
    const float* gq  = (const float*)d_in[10];
    const float* gk  = (const float*)d_in[11];
    float* out = (float*)d_out;

    __half *xh, *xl, *ch, *cl, *wqt, *wkvt, *wot, *qh, *ql, *kh, *vt, *ah, *al;
    float *qbuf, *kvbuf, *bkv;
    cudaGetSymbolAddress((void**)&xh, g_xh);     cudaGetSymbolAddress((void**)&xl, g_xl);
    cudaGetSymbolAddress((void**)&ch, g_ch);     cudaGetSymbolAddress((void**)&cl, g_cl);
    cudaGetSymbolAddress((void**)&wqt, g_wqt);   cudaGetSymbolAddress((void**)&wkvt, g_wkvt);
    cudaGetSymbolAddress((void**)&wot, g_wot);
    cudaGetSymbolAddress((void**)&qbuf, g_qbuf); cudaGetSymbolAddress((void**)&kvbuf, g_kvbuf);
    cudaGetSymbolAddress((void**)&bkv, g_bkv);
    cudaGetSymbolAddress((void**)&qh, g_qh);     cudaGetSymbolAddress((void**)&ql, g_ql);
    cudaGetSymbolAddress((void**)&kh, g_kh);     cudaGetSymbolAddress((void**)&vt, g_vt);
    cudaGetSymbolAddress((void**)&ah, g_ah);     cudaGetSymbolAddress((void**)&al, g_al);

    cudaFuncSetAttribute(gemm_mma_split, cudaFuncAttributeMaxDynamicSharedMemorySize, SMEM_GEMM);
    cudaFuncSetAttribute(flash_attn_kernel, cudaFuncAttributeMaxDynamicSharedMemorySize, SMEM_FLASH);

    const float scale = 1.0f / sqrtf((float)HD);

    // -- operand prep
    split4h_kernel<<<(LQ * DIMC) / 1024, 256>>>(x, xh, xl);
    split4h_kernel<<<(SK * CTXD) / 1024, 256>>>(ctx, ch, cl);
    round_transpose_kernel<<<dim3(DIMC / 32, DIMC / 32), 256>>>(Wq, wqt, DIMC, DIMC, DIMC);
    round_transpose_kernel<<<dim3(DIMC / 32, CTXD / 32), 256>>>(Wk, wkvt, CTXD, DIMC, DIMC);
    round_transpose_kernel<<<dim3(DIMC / 32, CTXD / 32), 256>>>(
        Wv, wkvt + (size_t)DIMC * CTXD, CTXD, DIMC, DIMC);
    round_transpose_kernel<<<dim3(DIMC / 32, DIMC / 32), 256>>>(Wo, wot, DIMC, DIMC, DIMC);
    concat_bias_kernel<<<(2 * DIMC) / 256, 256>>>(bk, bv, bkv);

    // -- Q projection
    gemm_mma_split<<<dim3(DIMC / 128, LQ / 128, 1), 256, SMEM_GEMM>>>(
        xh, xl, wqt, bq, qbuf, DIMC, DIMC, DIMC, DIMC, 1.0f, 0, 0, 0);
    // -- merged KV projection
    gemm_mma_split<<<dim3((2 * DIMC) / 128, SK / 128, 1), 256, SMEM_GEMM>>>(
        ch, cl, wkvt, bkv, kvbuf, CTXD, CTXD, CTXD, 2 * DIMC, 1.0f, 0, 0, 0);

    // -- RMSNorm: Q pre-scaled by 1/sqrt(HD) -> hi+lo; K -> hi only
    rmsnorm_split_kernel<<<LQ, 256>>>(qbuf, gq, qh, ql, DIMC, scale);
    rmsnorm_split_kernel<<<SK, 256>>>(kvbuf, gk, kh, nullptr, 2 * DIMC, 1.0f);
    // -- V transpose -> vt[h*128+d][s]
    round_transpose_kernel<<<dim3(DIMC / 32, SK / 32), 256>>>(
        kvbuf + DIMC, vt, SK, DIMC, 2 * DIMC);

    // -- fused attention (writes fp16 hi/lo of attn output directly)
    flash_attn_kernel<<<dim3(NH, LQ / 128), 256, SMEM_FLASH>>>(qh, ql, kh, vt, ah, al);

    // -- O projection
    gemm_mma_split<<<dim3(DIMC / 128, LQ / 128, 1), 256, SMEM_GEMM>>>(
        ah, al, wot, bo, out, DIMC, DIMC, DIMC, DIMC, 1.0f, 0, 0, 0);
}